// round 16
// baseline (speedup 1.0000x reference)
#include <cuda_runtime.h>
#include <cstdint>

#define BB  16
#define NN  4096
#define NP  1024
#define CC  64
#define NSMP 32
#define R2  0.04f
#define BPB 18           // ball blocks per batch (16*18 = 288 blocks, 2 CTA/SM)
#define CPB 57           // centers per ball block (18*57 >= 1024)
#define BTH 768          // ball threads per block (24 warps)

// idx scratch: 16*1024*32 ints = 2 MB
__device__ int g_idx[BB * NP * NSMP];

// Packed f32x2 helpers (Blackwell sm_103a). Same .rn rounding as scalar.
#define ADD2(out, a, b) asm("add.rn.f32x2 %0, %1, %2;" : "=l"(out) : "l"(a), "l"(b))
#define MUL2(out, a, b) asm("mul.rn.f32x2 %0, %1, %2;" : "=l"(out) : "l"(a), "l"(b))
#define UNPK2(lo, hi, in) asm("mov.b64 {%0, %1}, %2;" : "=r"(lo), "=r"(hi) : "l"(in))
#define PK2(out, lo, hi) asm("mov.b64 %0, {%1, %2};" : "=l"(out) : "r"(lo), "r"(hi))

// ---------------------------------------------------------------------------
// Kernel 1: ball query. Grid = 16 x 18 = 288 blocks, 768 threads, 2 CTAs/SM
// (48 warps/SM for inter-warp latency hiding on top of the R15 intra-warp
// 2-chunk software pipeline). Warp per center + work stealing.
// ---------------------------------------------------------------------------
__global__ void __launch_bounds__(BTH, 2) ball_query_kernel(
    const float* __restrict__ xyz, const float* __restrict__ new_xyz)
{
    __shared__ __align__(16) float xs[NN];
    __shared__ __align__(16) float ys[NN];
    __shared__ __align__(16) float zs[NN];
    __shared__ int s_next;

    const int b   = blockIdx.x / BPB;
    const int blk = blockIdx.x - b * BPB;
    const int c0  = blk * CPB;
    const int cpb = min(CPB, NP - c0);

    if (threadIdx.x == 0) s_next = BTH / 32;

    const float* xb = xyz + b * NN * 3;
    for (int t = threadIdx.x; t < NN * 3; t += BTH) {
        float v = xb[t];
        int n = t / 3;
        int c = t - n * 3;
        if (c == 0)      xs[n] = v;
        else if (c == 1) ys[n] = v;
        else             zs[n] = v;
    }
    __syncthreads();

    const int warp = threadIdx.x >> 5;
    const int lane = threadIdx.x & 31;
    const unsigned ltmask = (1u << lane) - 1u;

    int ci = warp;

    #pragma unroll 1
    while (ci < cpb) {
        const int np = c0 + ci;
        const float* c3 = new_xyz + ((b << 10) + np) * 3;
        const float cx = c3[0];
        const float cy = c3[1];
        const float cz = c3[2];

        uint64_t ncx2, ncy2, ncz2;
        {
            unsigned nx = __float_as_uint(-cx);
            unsigned ny = __float_as_uint(-cy);
            unsigned nz = __float_as_uint(-cz);
            PK2(ncx2, nx, nx);
            PK2(ncy2, ny, ny);
            PK2(ncz2, nz, nz);
        }

        int cnt = 0;
        int firstIdx = 0;
        int* orow = g_idx + (((b << 10) + np) << 5);

        // 16 super-chunks of 256 points (2 x 128-pt chunks, pipelined)
        #pragma unroll 1
        for (int sc = 0; sc < NN / 256; sc++) {
            const int baseA = (sc << 8) + (lane << 2);
            const int baseB = baseA + 128;

            // loads for BOTH chunks up front (12 LDS.128 in flight)
            ulonglong2 xvA = *(const ulonglong2*)(xs + baseA);
            ulonglong2 yvA = *(const ulonglong2*)(ys + baseA);
            ulonglong2 zvA = *(const ulonglong2*)(zs + baseA);
            ulonglong2 xvB = *(const ulonglong2*)(xs + baseB);
            ulonglong2 yvB = *(const ulonglong2*)(ys + baseB);
            ulonglong2 zvB = *(const ulonglong2*)(zs + baseB);

            // ---- chunk A math + bookkeeping (B loads still in flight) ----
            {
                uint64_t dx0, dy0, dz0, dx1, dy1, dz1, s0, s1;
                ADD2(dx0, xvA.x, ncx2);  ADD2(dx1, xvA.y, ncx2);
                ADD2(dy0, yvA.x, ncy2);  ADD2(dy1, yvA.y, ncy2);
                ADD2(dz0, zvA.x, ncz2);  ADD2(dz1, zvA.y, ncz2);
                MUL2(dx0, dx0, dx0);     MUL2(dx1, dx1, dx1);
                MUL2(dy0, dy0, dy0);     MUL2(dy1, dy1, dy1);
                MUL2(dz0, dz0, dz0);     MUL2(dz1, dz1, dz1);
                ADD2(s0, dx0, dy0);      ADD2(s1, dx1, dy1);
                ADD2(s0, s0, dz0);       ADD2(s1, s1, dz1);

                unsigned u0, u1, u2, u3;
                UNPK2(u0, u1, s0);
                UNPK2(u2, u3, s1);
                bool m0 = __uint_as_float(u0) < R2;
                bool m1 = __uint_as_float(u1) < R2;
                bool m2 = __uint_as_float(u2) < R2;
                bool m3 = __uint_as_float(u3) < R2;

                const unsigned b0 = __ballot_sync(0xffffffffu, m0);
                const unsigned b1 = __ballot_sync(0xffffffffu, m1);
                const unsigned b2 = __ballot_sync(0xffffffffu, m2);
                const unsigned b3 = __ballot_sync(0xffffffffu, m3);

                if (cnt == 0) {
                    unsigned any = b0 | b1 | b2 | b3;
                    if (any) {
                        int f = 1 << 30;
                        if (b0) f = min(f, ((__ffs(b0) - 1) << 2) + 0);
                        if (b1) f = min(f, ((__ffs(b1) - 1) << 2) + 1);
                        if (b2) f = min(f, ((__ffs(b2) - 1) << 2) + 2);
                        if (b3) f = min(f, ((__ffs(b3) - 1) << 2) + 3);
                        firstIdx = (sc << 8) + f;
                    }
                }

                int pre = __popc(b0 & ltmask) + __popc(b1 & ltmask)
                        + __popc(b2 & ltmask) + __popc(b3 & ltmask);

                int s;
                s = cnt + pre; pre += (int)m0;
                if (m0 & (s < NSMP)) orow[s] = baseA + 0;
                s = cnt + pre; pre += (int)m1;
                if (m1 & (s < NSMP)) orow[s] = baseA + 1;
                s = cnt + pre; pre += (int)m2;
                if (m2 & (s < NSMP)) orow[s] = baseA + 2;
                s = cnt + pre; pre += (int)m3;
                if (m3 & (s < NSMP)) orow[s] = baseA + 3;

                cnt += __popc(b0) + __popc(b1) + __popc(b2) + __popc(b3);
            }

            // ---- chunk B math + bookkeeping ----
            {
                uint64_t dx0, dy0, dz0, dx1, dy1, dz1, s0, s1;
                ADD2(dx0, xvB.x, ncx2);  ADD2(dx1, xvB.y, ncx2);
                ADD2(dy0, yvB.x, ncy2);  ADD2(dy1, yvB.y, ncy2);
                ADD2(dz0, zvB.x, ncz2);  ADD2(dz1, zvB.y, ncz2);
                MUL2(dx0, dx0, dx0);     MUL2(dx1, dx1, dx1);
                MUL2(dy0, dy0, dy0);     MUL2(dy1, dy1, dy1);
                MUL2(dz0, dz0, dz0);     MUL2(dz1, dz1, dz1);
                ADD2(s0, dx0, dy0);      ADD2(s1, dx1, dy1);
                ADD2(s0, s0, dz0);       ADD2(s1, s1, dz1);

                unsigned u0, u1, u2, u3;
                UNPK2(u0, u1, s0);
                UNPK2(u2, u3, s1);
                bool m0 = __uint_as_float(u0) < R2;
                bool m1 = __uint_as_float(u1) < R2;
                bool m2 = __uint_as_float(u2) < R2;
                bool m3 = __uint_as_float(u3) < R2;

                const unsigned b0 = __ballot_sync(0xffffffffu, m0);
                const unsigned b1 = __ballot_sync(0xffffffffu, m1);
                const unsigned b2 = __ballot_sync(0xffffffffu, m2);
                const unsigned b3 = __ballot_sync(0xffffffffu, m3);

                if (cnt == 0) {
                    unsigned any = b0 | b1 | b2 | b3;
                    if (any) {
                        int f = 1 << 30;
                        if (b0) f = min(f, ((__ffs(b0) - 1) << 2) + 0);
                        if (b1) f = min(f, ((__ffs(b1) - 1) << 2) + 1);
                        if (b2) f = min(f, ((__ffs(b2) - 1) << 2) + 2);
                        if (b3) f = min(f, ((__ffs(b3) - 1) << 2) + 3);
                        firstIdx = (sc << 8) + 128 + f;
                    }
                }

                int pre = __popc(b0 & ltmask) + __popc(b1 & ltmask)
                        + __popc(b2 & ltmask) + __popc(b3 & ltmask);

                int s;
                s = cnt + pre; pre += (int)m0;
                if (m0 & (s < NSMP)) orow[s] = baseB + 0;
                s = cnt + pre; pre += (int)m1;
                if (m1 & (s < NSMP)) orow[s] = baseB + 1;
                s = cnt + pre; pre += (int)m2;
                if (m2 & (s < NSMP)) orow[s] = baseB + 2;
                s = cnt + pre; pre += (int)m3;
                if (m3 & (s < NSMP)) orow[s] = baseB + 3;

                cnt += __popc(b0) + __popc(b1) + __popc(b2) + __popc(b3);
            }

            if (cnt >= NSMP) break;   // uniform (ballot-derived)
        }

        if (cnt < NSMP) {
            for (int s = cnt + lane; s < NSMP; s += 32) orow[s] = firstIdx;
        }

        int nc;
        if (lane == 0) nc = atomicAdd(&s_next, 1);
        ci = __shfl_sync(0xffffffffu, nc, 0);
    }
}

// ---------------------------------------------------------------------------
// Kernel 2 (frozen R12 best): gather + group. 1024 threads/block, 2 CTAs/SM.
// Register-transpose staging, 4x LDS.128 gather, register transpose,
// 1x STG.128 per channel.
// ---------------------------------------------------------------------------
__global__ void __launch_bounds__(1024, 2) group_kernel(
    const float* __restrict__ xyz, const float* __restrict__ new_xyz,
    const float* __restrict__ points, float* __restrict__ out)
{
    extern __shared__ float sm[];   // 64 KB
    const int tile = blockIdx.x % 17;
    const int b    = blockIdx.x / 17;
    const int tid  = threadIdx.x;
    const int warp = tid >> 5;
    const int lane = tid & 31;
    const int S    = NP * NSMP;

    const int sub  = lane >> 3;
    const int soff = (lane & 7) << 2;

    if (tile < 16) {
        const float* pb = points + (b * CC + tile * 4) * NN;
        #pragma unroll
        for (int j = 0; j < 4; j++) {
            int n = tid + j * 1024;
            float4 v;
            v.x = pb[0 * NN + n];
            v.y = pb[1 * NN + n];
            v.z = pb[2 * NN + n];
            v.w = pb[3 * NN + n];
            *(float4*)(sm + (n << 2)) = v;
        }
        __syncthreads();

        const int obase = (b * 67 + 3 + tile * 4) * S;
        int g = warp;
        const int np0 = (g << 2) + sub;
        int4 id = *(const int4*)(g_idx + (((b << 10) + np0) << 5) + soff);
        #pragma unroll 1
        while (g < 256) {
            const int gn = g + 32;
            int4 idn;
            if (gn < 256) {
                const int npn = (gn << 2) + sub;
                idn = *(const int4*)(g_idx + (((b << 10) + npn) << 5) + soff);
            }

            const float4 p0 = *(const float4*)(sm + (id.x << 2));
            const float4 p1 = *(const float4*)(sm + (id.y << 2));
            const float4 p2 = *(const float4*)(sm + (id.z << 2));
            const float4 p3 = *(const float4*)(sm + (id.w << 2));

            float4* o = (float4*)(out + obase + (g << 7) + (lane << 2));
            const int S4 = S >> 2;
            float4 t0 = make_float4(p0.x, p1.x, p2.x, p3.x);
            float4 t1 = make_float4(p0.y, p1.y, p2.y, p3.y);
            float4 t2 = make_float4(p0.z, p1.z, p2.z, p3.z);
            float4 t3 = make_float4(p0.w, p1.w, p2.w, p3.w);
            __stcs(o + 0 * S4, t0);
            __stcs(o + 1 * S4, t1);
            __stcs(o + 2 * S4, t2);
            __stcs(o + 3 * S4, t3);

            id = idn;
            g = gn;
        }
    } else {
        const float* xb = xyz + b * NN * 3;
        #pragma unroll
        for (int j = 0; j < 4; j++) {
            int n = tid + j * 1024;
            float4 v;
            v.x = xb[n * 3 + 0];
            v.y = xb[n * 3 + 1];
            v.z = xb[n * 3 + 2];
            v.w = 0.0f;
            *(float4*)(sm + (n << 2)) = v;
        }
        __syncthreads();

        const int obase = (b * 67) * S;
        int g = warp;
        const int np0 = (g << 2) + sub;
        int4 id = *(const int4*)(g_idx + (((b << 10) + np0) << 5) + soff);
        #pragma unroll 1
        while (g < 256) {
            const int gn = g + 32;
            int4 idn;
            if (gn < 256) {
                const int npn = (gn << 2) + sub;
                idn = *(const int4*)(g_idx + (((b << 10) + npn) << 5) + soff);
            }

            const int np = (g << 2) + sub;
            const float* c3 = new_xyz + ((b << 10) + np) * 3;
            const float cx = __ldg(c3 + 0);
            const float cy = __ldg(c3 + 1);
            const float cz = __ldg(c3 + 2);

            const float4 p0 = *(const float4*)(sm + (id.x << 2));
            const float4 p1 = *(const float4*)(sm + (id.y << 2));
            const float4 p2 = *(const float4*)(sm + (id.z << 2));
            const float4 p3 = *(const float4*)(sm + (id.w << 2));

            float4* o = (float4*)(out + obase + (g << 7) + (lane << 2));
            const int S4 = S >> 2;
            float4 t0 = make_float4(p0.x - cx, p1.x - cx, p2.x - cx, p3.x - cx);
            float4 t1 = make_float4(p0.y - cy, p1.y - cy, p2.y - cy, p3.y - cy);
            float4 t2 = make_float4(p0.z - cz, p1.z - cz, p2.z - cz, p3.z - cz);
            __stcs(o + 0 * S4, t0);
            __stcs(o + 1 * S4, t1);
            __stcs(o + 2 * S4, t2);

            id = idn;
            g = gn;
        }
    }
}

extern "C" void kernel_launch(void* const* d_in, const int* in_sizes, int n_in,
                              void* d_out, int out_size)
{
    const float* xyz = nullptr;
    const float* new_xyz = nullptr;
    const float* points = nullptr;
    for (int i = 0; i < n_in; i++) {
        if (in_sizes[i] == BB * NN * 3)      xyz     = (const float*)d_in[i];
        else if (in_sizes[i] == BB * NP * 3) new_xyz = (const float*)d_in[i];
        else if (in_sizes[i] == BB * CC * NN) points = (const float*)d_in[i];
    }
    float* out = (float*)d_out;

    cudaFuncSetAttribute(group_kernel, cudaFuncAttributeMaxDynamicSharedMemorySize, 65536);

    ball_query_kernel<<<BB * BPB, BTH>>>(xyz, new_xyz);
    group_kernel<<<BB * 17, 1024, 65536>>>(xyz, new_xyz, points, out);
}

// round 17
// speedup vs baseline: 1.1212x; 1.1212x over previous
#include <cuda_runtime.h>
#include <cstdint>

#define BB  16
#define NN  4096
#define NP  1024
#define CC  64
#define NSMP 32
#define R2  0.04f
#define BPB 9            // ball blocks per batch (16*9 = 144 blocks = 1 wave)
#define CPB 114          // centers per ball block (9*114 >= 1024)

// idx scratch: 16*1024*32 ints = 2 MB
__device__ int g_idx[BB * NP * NSMP];

// Packed f32x2 helpers (Blackwell sm_103a). Same .rn rounding as scalar.
#define ADD2(out, a, b) asm("add.rn.f32x2 %0, %1, %2;" : "=l"(out) : "l"(a), "l"(b))
#define MUL2(out, a, b) asm("mul.rn.f32x2 %0, %1, %2;" : "=l"(out) : "l"(a), "l"(b))
#define UNPK2(lo, hi, in) asm("mov.b64 {%0, %1}, %2;" : "=r"(lo), "=r"(hi) : "l"(in))
#define PK2(out, lo, hi) asm("mov.b64 %0, {%1, %2};" : "=l"(out) : "r"(lo), "r"(hi))

// ---------------------------------------------------------------------------
// Kernel 1 (R15 winner): ball query. Grid = 16 x 9 = 144 blocks (one wave),
// 1024 threads. Warp per center + work stealing; packed f32x2 distance math.
// Software-pipelined 2 chunks/iter: chunk k+1's LDS issued before chunk k's
// bookkeeping to overlap load latency with the serial ballot/store section.
// ---------------------------------------------------------------------------
__global__ void __launch_bounds__(1024) ball_query_kernel(
    const float* __restrict__ xyz, const float* __restrict__ new_xyz)
{
    __shared__ __align__(16) float xs[NN];
    __shared__ __align__(16) float ys[NN];
    __shared__ __align__(16) float zs[NN];
    __shared__ int s_next;

    const int b   = blockIdx.x / BPB;
    const int blk = blockIdx.x - b * BPB;
    const int c0  = blk * CPB;
    const int cpb = min(CPB, NP - c0);

    if (threadIdx.x == 0) s_next = 32;

    const float* xb = xyz + b * NN * 3;
    for (int t = threadIdx.x; t < NN * 3; t += 1024) {
        float v = xb[t];
        int n = t / 3;
        int c = t - n * 3;
        if (c == 0)      xs[n] = v;
        else if (c == 1) ys[n] = v;
        else             zs[n] = v;
    }
    __syncthreads();

    const int warp = threadIdx.x >> 5;
    const int lane = threadIdx.x & 31;
    const unsigned ltmask = (1u << lane) - 1u;

    int ci = warp;

    #pragma unroll 1
    while (ci < cpb) {
        const int np = c0 + ci;
        const float* c3 = new_xyz + ((b << 10) + np) * 3;
        const float cx = c3[0];
        const float cy = c3[1];
        const float cz = c3[2];

        uint64_t ncx2, ncy2, ncz2;
        {
            unsigned nx = __float_as_uint(-cx);
            unsigned ny = __float_as_uint(-cy);
            unsigned nz = __float_as_uint(-cz);
            PK2(ncx2, nx, nx);
            PK2(ncy2, ny, ny);
            PK2(ncz2, nz, nz);
        }

        int cnt = 0;
        int firstIdx = 0;
        int* orow = g_idx + (((b << 10) + np) << 5);

        // 16 super-chunks of 256 points (2 x 128-pt chunks, pipelined)
        #pragma unroll 1
        for (int sc = 0; sc < NN / 256; sc++) {
            const int baseA = (sc << 8) + (lane << 2);
            const int baseB = baseA + 128;

            // loads for BOTH chunks up front (12 LDS.128 in flight)
            ulonglong2 xvA = *(const ulonglong2*)(xs + baseA);
            ulonglong2 yvA = *(const ulonglong2*)(ys + baseA);
            ulonglong2 zvA = *(const ulonglong2*)(zs + baseA);
            ulonglong2 xvB = *(const ulonglong2*)(xs + baseB);
            ulonglong2 yvB = *(const ulonglong2*)(ys + baseB);
            ulonglong2 zvB = *(const ulonglong2*)(zs + baseB);

            // ---- chunk A math + bookkeeping (B loads still in flight) ----
            {
                uint64_t dx0, dy0, dz0, dx1, dy1, dz1, s0, s1;
                ADD2(dx0, xvA.x, ncx2);  ADD2(dx1, xvA.y, ncx2);
                ADD2(dy0, yvA.x, ncy2);  ADD2(dy1, yvA.y, ncy2);
                ADD2(dz0, zvA.x, ncz2);  ADD2(dz1, zvA.y, ncz2);
                MUL2(dx0, dx0, dx0);     MUL2(dx1, dx1, dx1);
                MUL2(dy0, dy0, dy0);     MUL2(dy1, dy1, dy1);
                MUL2(dz0, dz0, dz0);     MUL2(dz1, dz1, dz1);
                ADD2(s0, dx0, dy0);      ADD2(s1, dx1, dy1);
                ADD2(s0, s0, dz0);       ADD2(s1, s1, dz1);

                unsigned u0, u1, u2, u3;
                UNPK2(u0, u1, s0);
                UNPK2(u2, u3, s1);
                bool m0 = __uint_as_float(u0) < R2;
                bool m1 = __uint_as_float(u1) < R2;
                bool m2 = __uint_as_float(u2) < R2;
                bool m3 = __uint_as_float(u3) < R2;

                const unsigned b0 = __ballot_sync(0xffffffffu, m0);
                const unsigned b1 = __ballot_sync(0xffffffffu, m1);
                const unsigned b2 = __ballot_sync(0xffffffffu, m2);
                const unsigned b3 = __ballot_sync(0xffffffffu, m3);

                if (cnt == 0) {
                    unsigned any = b0 | b1 | b2 | b3;
                    if (any) {
                        int f = 1 << 30;
                        if (b0) f = min(f, ((__ffs(b0) - 1) << 2) + 0);
                        if (b1) f = min(f, ((__ffs(b1) - 1) << 2) + 1);
                        if (b2) f = min(f, ((__ffs(b2) - 1) << 2) + 2);
                        if (b3) f = min(f, ((__ffs(b3) - 1) << 2) + 3);
                        firstIdx = (sc << 8) + f;
                    }
                }

                int pre = __popc(b0 & ltmask) + __popc(b1 & ltmask)
                        + __popc(b2 & ltmask) + __popc(b3 & ltmask);

                int s;
                s = cnt + pre; pre += (int)m0;
                if (m0 & (s < NSMP)) orow[s] = baseA + 0;
                s = cnt + pre; pre += (int)m1;
                if (m1 & (s < NSMP)) orow[s] = baseA + 1;
                s = cnt + pre; pre += (int)m2;
                if (m2 & (s < NSMP)) orow[s] = baseA + 2;
                s = cnt + pre; pre += (int)m3;
                if (m3 & (s < NSMP)) orow[s] = baseA + 3;

                cnt += __popc(b0) + __popc(b1) + __popc(b2) + __popc(b3);
            }

            // ---- chunk B math + bookkeeping ----
            {
                uint64_t dx0, dy0, dz0, dx1, dy1, dz1, s0, s1;
                ADD2(dx0, xvB.x, ncx2);  ADD2(dx1, xvB.y, ncx2);
                ADD2(dy0, yvB.x, ncy2);  ADD2(dy1, yvB.y, ncy2);
                ADD2(dz0, zvB.x, ncz2);  ADD2(dz1, zvB.y, ncz2);
                MUL2(dx0, dx0, dx0);     MUL2(dx1, dx1, dx1);
                MUL2(dy0, dy0, dy0);     MUL2(dy1, dy1, dy1);
                MUL2(dz0, dz0, dz0);     MUL2(dz1, dz1, dz1);
                ADD2(s0, dx0, dy0);      ADD2(s1, dx1, dy1);
                ADD2(s0, s0, dz0);       ADD2(s1, s1, dz1);

                unsigned u0, u1, u2, u3;
                UNPK2(u0, u1, s0);
                UNPK2(u2, u3, s1);
                bool m0 = __uint_as_float(u0) < R2;
                bool m1 = __uint_as_float(u1) < R2;
                bool m2 = __uint_as_float(u2) < R2;
                bool m3 = __uint_as_float(u3) < R2;

                const unsigned b0 = __ballot_sync(0xffffffffu, m0);
                const unsigned b1 = __ballot_sync(0xffffffffu, m1);
                const unsigned b2 = __ballot_sync(0xffffffffu, m2);
                const unsigned b3 = __ballot_sync(0xffffffffu, m3);

                if (cnt == 0) {
                    unsigned any = b0 | b1 | b2 | b3;
                    if (any) {
                        int f = 1 << 30;
                        if (b0) f = min(f, ((__ffs(b0) - 1) << 2) + 0);
                        if (b1) f = min(f, ((__ffs(b1) - 1) << 2) + 1);
                        if (b2) f = min(f, ((__ffs(b2) - 1) << 2) + 2);
                        if (b3) f = min(f, ((__ffs(b3) - 1) << 2) + 3);
                        firstIdx = (sc << 8) + 128 + f;
                    }
                }

                int pre = __popc(b0 & ltmask) + __popc(b1 & ltmask)
                        + __popc(b2 & ltmask) + __popc(b3 & ltmask);

                int s;
                s = cnt + pre; pre += (int)m0;
                if (m0 & (s < NSMP)) orow[s] = baseB + 0;
                s = cnt + pre; pre += (int)m1;
                if (m1 & (s < NSMP)) orow[s] = baseB + 1;
                s = cnt + pre; pre += (int)m2;
                if (m2 & (s < NSMP)) orow[s] = baseB + 2;
                s = cnt + pre; pre += (int)m3;
                if (m3 & (s < NSMP)) orow[s] = baseB + 3;

                cnt += __popc(b0) + __popc(b1) + __popc(b2) + __popc(b3);
            }

            if (cnt >= NSMP) break;   // uniform (ballot-derived)
        }

        if (cnt < NSMP) {
            for (int s = cnt + lane; s < NSMP; s += 32) orow[s] = firstIdx;
        }

        int nc;
        if (lane == 0) nc = atomicAdd(&s_next, 1);
        ci = __shfl_sync(0xffffffffu, nc, 0);
    }
}

// ---------------------------------------------------------------------------
// Kernel 2 (frozen R12 best): gather + group. 1024 threads/block, 2 CTAs/SM.
// Register-transpose staging, 4x LDS.128 gather, register transpose,
// 1x STG.128 per channel.
// ---------------------------------------------------------------------------
__global__ void __launch_bounds__(1024, 2) group_kernel(
    const float* __restrict__ xyz, const float* __restrict__ new_xyz,
    const float* __restrict__ points, float* __restrict__ out)
{
    extern __shared__ float sm[];   // 64 KB
    const int tile = blockIdx.x % 17;
    const int b    = blockIdx.x / 17;
    const int tid  = threadIdx.x;
    const int warp = tid >> 5;
    const int lane = tid & 31;
    const int S    = NP * NSMP;

    const int sub  = lane >> 3;
    const int soff = (lane & 7) << 2;

    if (tile < 16) {
        const float* pb = points + (b * CC + tile * 4) * NN;
        #pragma unroll
        for (int j = 0; j < 4; j++) {
            int n = tid + j * 1024;
            float4 v;
            v.x = pb[0 * NN + n];
            v.y = pb[1 * NN + n];
            v.z = pb[2 * NN + n];
            v.w = pb[3 * NN + n];
            *(float4*)(sm + (n << 2)) = v;
        }
        __syncthreads();

        const int obase = (b * 67 + 3 + tile * 4) * S;
        int g = warp;
        const int np0 = (g << 2) + sub;
        int4 id = *(const int4*)(g_idx + (((b << 10) + np0) << 5) + soff);
        #pragma unroll 1
        while (g < 256) {
            const int gn = g + 32;
            int4 idn;
            if (gn < 256) {
                const int npn = (gn << 2) + sub;
                idn = *(const int4*)(g_idx + (((b << 10) + npn) << 5) + soff);
            }

            const float4 p0 = *(const float4*)(sm + (id.x << 2));
            const float4 p1 = *(const float4*)(sm + (id.y << 2));
            const float4 p2 = *(const float4*)(sm + (id.z << 2));
            const float4 p3 = *(const float4*)(sm + (id.w << 2));

            float4* o = (float4*)(out + obase + (g << 7) + (lane << 2));
            const int S4 = S >> 2;
            float4 t0 = make_float4(p0.x, p1.x, p2.x, p3.x);
            float4 t1 = make_float4(p0.y, p1.y, p2.y, p3.y);
            float4 t2 = make_float4(p0.z, p1.z, p2.z, p3.z);
            float4 t3 = make_float4(p0.w, p1.w, p2.w, p3.w);
            __stcs(o + 0 * S4, t0);
            __stcs(o + 1 * S4, t1);
            __stcs(o + 2 * S4, t2);
            __stcs(o + 3 * S4, t3);

            id = idn;
            g = gn;
        }
    } else {
        const float* xb = xyz + b * NN * 3;
        #pragma unroll
        for (int j = 0; j < 4; j++) {
            int n = tid + j * 1024;
            float4 v;
            v.x = xb[n * 3 + 0];
            v.y = xb[n * 3 + 1];
            v.z = xb[n * 3 + 2];
            v.w = 0.0f;
            *(float4*)(sm + (n << 2)) = v;
        }
        __syncthreads();

        const int obase = (b * 67) * S;
        int g = warp;
        const int np0 = (g << 2) + sub;
        int4 id = *(const int4*)(g_idx + (((b << 10) + np0) << 5) + soff);
        #pragma unroll 1
        while (g < 256) {
            const int gn = g + 32;
            int4 idn;
            if (gn < 256) {
                const int npn = (gn << 2) + sub;
                idn = *(const int4*)(g_idx + (((b << 10) + npn) << 5) + soff);
            }

            const int np = (g << 2) + sub;
            const float* c3 = new_xyz + ((b << 10) + np) * 3;
            const float cx = __ldg(c3 + 0);
            const float cy = __ldg(c3 + 1);
            const float cz = __ldg(c3 + 2);

            const float4 p0 = *(const float4*)(sm + (id.x << 2));
            const float4 p1 = *(const float4*)(sm + (id.y << 2));
            const float4 p2 = *(const float4*)(sm + (id.z << 2));
            const float4 p3 = *(const float4*)(sm + (id.w << 2));

            float4* o = (float4*)(out + obase + (g << 7) + (lane << 2));
            const int S4 = S >> 2;
            float4 t0 = make_float4(p0.x - cx, p1.x - cx, p2.x - cx, p3.x - cx);
            float4 t1 = make_float4(p0.y - cy, p1.y - cy, p2.y - cy, p3.y - cy);
            float4 t2 = make_float4(p0.z - cz, p1.z - cz, p2.z - cz, p3.z - cz);
            __stcs(o + 0 * S4, t0);
            __stcs(o + 1 * S4, t1);
            __stcs(o + 2 * S4, t2);

            id = idn;
            g = gn;
        }
    }
}

extern "C" void kernel_launch(void* const* d_in, const int* in_sizes, int n_in,
                              void* d_out, int out_size)
{
    const float* xyz = nullptr;
    const float* new_xyz = nullptr;
    const float* points = nullptr;
    for (int i = 0; i < n_in; i++) {
        if (in_sizes[i] == BB * NN * 3)      xyz     = (const float*)d_in[i];
        else if (in_sizes[i] == BB * NP * 3) new_xyz = (const float*)d_in[i];
        else if (in_sizes[i] == BB * CC * NN) points = (const float*)d_in[i];
    }
    float* out = (float*)d_out;

    cudaFuncSetAttribute(group_kernel, cudaFuncAttributeMaxDynamicSharedMemorySize, 65536);

    ball_query_kernel<<<BB * BPB, 1024>>>(xyz, new_xyz);
    group_kernel<<<BB * 17, 1024, 65536>>>(xyz, new_xyz, points, out);
}